// round 5
// baseline (speedup 1.0000x reference)
#include <cuda_runtime.h>

#define Bn 8
#define Cn 128
#define Hn 64
#define Wn 64
#define NPIX (Bn*Hn*Wn)          // 32768
#define COUT 128

// ---- scratch (allocation-free: __device__ globals) ----
__device__ __align__(16) float g_xt[Bn*Hn*Wn*Cn];     // NHWC copy of x (16 MB)
__device__ __align__(16) float g_wt[9*Cn*COUT];       // w transposed: [k][c][o]
__device__ __align__(16) float g_wofft[9*4*Cn];       // w_off transposed: [tap][oc][c]
__device__ __align__(16) float g_off[NPIX*4];         // per-pixel {off0, off1, s1, s2}

// ---------------------------------------------------------------------------
// Kernel 1: weight transposes (tiny)
// ---------------------------------------------------------------------------
__global__ void wtrans_kernel(const float* __restrict__ w,
                              const float* __restrict__ w_off) {
    int tid = blockIdx.x * 256 + threadIdx.x;
    if (tid < 9*Cn*COUT) {
        int k = tid / (Cn*COUT);
        int r = tid % (Cn*COUT);
        int c = r / COUT;
        int o = r % COUT;
        g_wt[tid] = w[(o*Cn + c)*9 + k];      // w: [o][c][3][3]
    }
    if (tid < 9*4*Cn) {
        int tap = tid / (4*Cn);
        int r   = tid % (4*Cn);
        int oc  = r / Cn;
        int c   = r % Cn;
        g_wofft[tid] = w_off[(oc*Cn + c)*9 + tap];   // w_off: [5][c][3][3], oc<4 used
    }
}

// ---------------------------------------------------------------------------
// Kernel 2: NCHW -> NHWC transpose of x
// ---------------------------------------------------------------------------
__global__ void transpose_kernel(const float* __restrict__ x) {
    __shared__ float tile[32][33];
    int bh = blockIdx.z;
    int b = bh >> 6, h = bh & 63;
    int c0 = blockIdx.y * 32;
    int w0 = blockIdx.x * 32;
    int tx = threadIdx.x, ty = threadIdx.y;
    #pragma unroll
    for (int i = 0; i < 32; i += 8)
        tile[ty + i][tx] = x[((b*Cn + c0 + ty + i)*Hn + h)*Wn + w0 + tx];
    __syncthreads();
    #pragma unroll
    for (int i = 0; i < 32; i += 8)
        g_xt[((bh*Wn) + w0 + ty + i)*Cn + c0 + tx] = tile[tx][ty + i];
}

// ---------------------------------------------------------------------------
// Kernel 3: offset conv -> per-pixel params
// ---------------------------------------------------------------------------
__global__ __launch_bounds__(256) void offset_kernel(const float* __restrict__ b_off) {
    __shared__ float sw[9*4*Cn];     // 18 KB
    int tid = threadIdx.x;
    for (int i = tid; i < 9*4*Cn; i += 256) sw[i] = g_wofft[i];
    __syncthreads();

    int warp = tid >> 5, lane = tid & 31;
    int pix = blockIdx.x * 8 + warp;
    int b   = pix >> 12;
    int rem = pix & 4095;
    int h   = rem >> 6, w = rem & 63;

    float a0 = 0.f, a1 = 0.f, a2 = 0.f, a3 = 0.f;
    const float4* xt4 = (const float4*)g_xt;

    #pragma unroll
    for (int tap = 0; tap < 9; tap++) {
        int dy = tap/3 - 1, dx = tap%3 - 1;
        int yy = h + dy, xx = w + dx;
        if (yy < 0 || yy >= Hn || xx < 0 || xx >= Wn) continue;
        float4 v = xt4[((b*Hn + yy)*Wn + xx)*(Cn/4) + lane];
        const float4* wv = (const float4*)&sw[tap*4*Cn];
        float4 w0v = wv[0*32 + lane];
        float4 w1v = wv[1*32 + lane];
        float4 w2v = wv[2*32 + lane];
        float4 w3v = wv[3*32 + lane];
        a0 += v.x*w0v.x + v.y*w0v.y + v.z*w0v.z + v.w*w0v.w;
        a1 += v.x*w1v.x + v.y*w1v.y + v.z*w1v.z + v.w*w1v.w;
        a2 += v.x*w2v.x + v.y*w2v.y + v.z*w2v.z + v.w*w2v.w;
        a3 += v.x*w3v.x + v.y*w3v.y + v.z*w3v.z + v.w*w3v.w;
    }
    #pragma unroll
    for (int s = 16; s; s >>= 1) {
        a0 += __shfl_xor_sync(0xffffffffu, a0, s);
        a1 += __shfl_xor_sync(0xffffffffu, a1, s);
        a2 += __shfl_xor_sync(0xffffffffu, a2, s);
        a3 += __shfl_xor_sync(0xffffffffu, a3, s);
    }
    if (lane == 0) {
        float4 r;
        r.x = a0 + b_off[0];
        r.y = a1 + b_off[1];
        r.z = fmaxf(a2 + b_off[2], 0.f) + 1.f;
        r.w = fmaxf(a3 + b_off[3], 0.f) + 1.f;
        ((float4*)g_off)[pix] = r;
    }
}

// ---------------------------------------------------------------------------
// Kernel 4: fused bilinear sample + GEMM, FFMA2 (f32x2) + cp.async w staging.
// One block per (b,h) row: 64 pixels x 128 outs. 256 threads, 1 block/SM.
// smem: w double-buffer 2x64KB, s_dup [c][2*p (+pad)] 67.6KB (each value {v,v}).
// Per-thread tile: 8 o (4 o-pairs) x 4 pixels -> 16 f32x2 accumulators.
// ---------------------------------------------------------------------------
#define SW_ELEMS   (Cn*COUT)          // 16384 floats (64 KB)
#define ROWF       132                // s_dup row stride in floats (128 + pad, 16B-aligned)
#define SD_ELEMS   (Cn*ROWF)          // 16896 floats (67.6 KB)
#define SMEM_FLOATS (2*SW_ELEMS + SD_ELEMS + 64*4)
#define SMEM_BYTES  (SMEM_FLOATS*4)   // 199,680 B

typedef unsigned long long ull;

#define FMA2(d,a,b) asm("fma.rn.f32x2 %0, %1, %2, %0;" : "+l"(d) : "l"(a), "l"(b))

__device__ __forceinline__ ull dup2(float v) {
    ull d;
    asm("mov.b64 %0, {%1, %1};" : "=l"(d) : "f"(v));
    return d;
}
__device__ __forceinline__ float2 unpack2(ull d) {
    float2 f;
    asm("mov.b64 {%0, %1}, %2;" : "=f"(f.x), "=f"(f.y) : "l"(d));
    return f;
}
__device__ __forceinline__ void cp_async16(void* sdst, const void* gsrc) {
    unsigned saddr = (unsigned)__cvta_generic_to_shared(sdst);
    asm volatile("cp.async.cg.shared.global [%0], [%1], 16;" :: "r"(saddr), "l"(gsrc));
}
__device__ __forceinline__ void cp_commit() { asm volatile("cp.async.commit_group;"); }
__device__ __forceinline__ void cp_wait1()  { asm volatile("cp.async.wait_group 1;" ::: "memory"); }
__device__ __forceinline__ void cp_wait0()  { asm volatile("cp.async.wait_group 0;" ::: "memory"); }

__global__ __launch_bounds__(256, 1) void main_kernel(const float* __restrict__ bias,
                                                      float* __restrict__ out) {
    extern __shared__ float smem[];
    float* s_w   = smem;                         // 2 x [c][128]
    float* s_sd  = smem + 2*SW_ELEMS;            // [c][ROWF], values duplicated {v,v}
    float* s_off = smem + 2*SW_ELEMS + SD_ELEMS; // [64][4]

    int tid = threadIdx.x;
    int bh  = blockIdx.x;
    int b   = bh >> 6, h = bh & 63;

    if (tid < 64)
        ((float4*)s_off)[tid] = ((const float4*)g_off)[(bh << 6) + tid];

    // preload w for k=0 into buffer 0
    {
        const float4* wsrc = (const float4*)g_wt;
        float4* wdst = (float4*)s_w;
        #pragma unroll
        for (int i = 0; i < 16; i++)
            cp_async16(&wdst[tid + i*256], &wsrc[tid + i*256]);
        cp_commit();
    }

    ull acc[4][4];   // [o-pair][pixel]
    #pragma unroll
    for (int i = 0; i < 4; i++)
        #pragma unroll
        for (int j = 0; j < 4; j++) acc[i][j] = 0ull;

    int sp = tid >> 2;         // sampling: pixel 0..63
    int sq = tid & 3;          // sampling: channel quarter (32 ch)
    int o0 = (tid & 15) * 8;   // gemm: 8 output channels (4 pairs)
    int p0 = (tid >> 4) * 4;   // gemm: 4 pixels

    const float4* xt4 = (const float4*)g_xt;

    #pragma unroll 1
    for (int k = 0; k < 9; k++) {
        __syncthreads();   // GEMM k-1 done reading s_w buf & s_sd; s_off ready (k=0)

        // ---- kick cp.async for w(k+1) into the other buffer ----
        if (k < 8) {
            const float4* wsrc = (const float4*)(g_wt + (k+1)*SW_ELEMS);
            float4* wdst = (float4*)(s_w + ((k+1)&1)*SW_ELEMS);
            #pragma unroll
            for (int i = 0; i < 16; i++)
                cp_async16(&wdst[tid + i*256], &wsrc[tid + i*256]);
            cp_commit();
        }

        // ---- sample 32 channels of pixel sp, write duplicated pairs ----
        {
            float off0 = s_off[sp*4+0], off1 = s_off[sp*4+1];
            float sc1  = s_off[sp*4+2], sc2  = s_off[sp*4+3];
            int by = k/3 - 1, bx = k%3 - 1;
            float sk = (by != 0 && bx != 0) ? sc1 : ((by == 0 && bx == 0) ? 0.f : sc2);
            float py = (float)h  + (float)by * sk + off0;
            float px = (float)sp + (float)bx * sk + off1;
            float fy = floorf(py), fx = floorf(px);
            float wy = py - fy,    wx = px - fx;
            int y0 = (int)fy, x0 = (int)fx;
            float cw[4] = {(1.f-wy)*(1.f-wx), (1.f-wy)*wx, wy*(1.f-wx), wy*wx};

            float4 samp[8];
            #pragma unroll
            for (int i = 0; i < 8; i++) samp[i] = make_float4(0.f,0.f,0.f,0.f);

            #pragma unroll
            for (int j = 0; j < 4; j++) {
                int yc = y0 + (j >> 1);
                int xc = x0 + (j & 1);
                if (yc < 0 || yc >= Hn || xc < 0 || xc >= Wn) continue;
                const float4* src = xt4 + ((b*Hn + yc)*Wn + xc)*(Cn/4) + sq*8;
                float wj = cw[j];
                #pragma unroll
                for (int i = 0; i < 8; i++) {
                    float4 v = src[i];
                    samp[i].x += wj*v.x; samp[i].y += wj*v.y;
                    samp[i].z += wj*v.z; samp[i].w += wj*v.w;
                }
            }
            // write duplicated: channel c row, column 2*sp
            #pragma unroll
            for (int i = 0; i < 8; i++) {
                int c = sq*32 + i*4;
                *(ull*)(s_sd + (c+0)*ROWF + 2*sp) = dup2(samp[i].x);
                *(ull*)(s_sd + (c+1)*ROWF + 2*sp) = dup2(samp[i].y);
                *(ull*)(s_sd + (c+2)*ROWF + 2*sp) = dup2(samp[i].z);
                *(ull*)(s_sd + (c+3)*ROWF + 2*sp) = dup2(samp[i].w);
            }
        }

        if (k < 8) cp_wait1(); else cp_wait0();
        __syncthreads();

        // ---- GEMM: acc[op][p] += {w[c][o0+2op], w[c][o0+2op+1]} * {s[p][c], s[p][c]} ----
        const float* s_wk = s_w + (k&1)*SW_ELEMS;
        #pragma unroll 1
        for (int cc = 0; cc < Cn; cc += 4) {
            #pragma unroll
            for (int j = 0; j < 4; j++) {
                int c = cc + j;
                ulonglong2 wa = *(const ulonglong2*)(s_wk + c*COUT + o0);
                ulonglong2 wb = *(const ulonglong2*)(s_wk + c*COUT + o0 + 4);
                ulonglong2 sa = *(const ulonglong2*)(s_sd + c*ROWF + 2*p0);
                ulonglong2 sb = *(const ulonglong2*)(s_sd + c*ROWF + 2*p0 + 4);
                FMA2(acc[0][0], wa.x, sa.x); FMA2(acc[1][0], wa.y, sa.x);
                FMA2(acc[2][0], wb.x, sa.x); FMA2(acc[3][0], wb.y, sa.x);
                FMA2(acc[0][1], wa.x, sa.y); FMA2(acc[1][1], wa.y, sa.y);
                FMA2(acc[2][1], wb.x, sa.y); FMA2(acc[3][1], wb.y, sa.y);
                FMA2(acc[0][2], wa.x, sb.x); FMA2(acc[1][2], wa.y, sb.x);
                FMA2(acc[2][2], wb.x, sb.x); FMA2(acc[3][2], wb.y, sb.x);
                FMA2(acc[0][3], wa.x, sb.y); FMA2(acc[1][3], wa.y, sb.y);
                FMA2(acc[2][3], wb.x, sb.y); FMA2(acc[3][3], wb.y, sb.y);
            }
        }
    }

    // ---- epilogue: out NCHW. acc[op][p]: lo -> o0+2op, hi -> o0+2op+1 ----
    #pragma unroll
    for (int op = 0; op < 4; op++) {
        float2 f0 = unpack2(acc[op][0]);
        float2 f1 = unpack2(acc[op][1]);
        float2 f2 = unpack2(acc[op][2]);
        float2 f3 = unpack2(acc[op][3]);
        int oA = o0 + 2*op, oB = oA + 1;
        float bA = bias[oA], bB = bias[oB];
        float4 rA = make_float4(f0.x+bA, f1.x+bA, f2.x+bA, f3.x+bA);
        float4 rB = make_float4(f0.y+bB, f1.y+bB, f2.y+bB, f3.y+bB);
        *(float4*)&out[((b*COUT + oA)*Hn + h)*Wn + p0] = rA;
        *(float4*)&out[((b*COUT + oB)*Hn + h)*Wn + p0] = rB;
    }
}

// ---------------------------------------------------------------------------
extern "C" void kernel_launch(void* const* d_in, const int* in_sizes, int n_in,
                              void* d_out, int out_size) {
    const float* x     = (const float*)d_in[0];
    const float* w_off = (const float*)d_in[1];
    const float* b_off = (const float*)d_in[2];
    const float* w     = (const float*)d_in[3];
    const float* bias  = (const float*)d_in[4];
    float* out = (float*)d_out;

    cudaFuncSetAttribute(main_kernel, cudaFuncAttributeMaxDynamicSharedMemorySize, SMEM_BYTES);

    wtrans_kernel<<<(9*Cn*COUT + 255)/256, 256>>>(w, w_off);
    transpose_kernel<<<dim3(2, 4, Bn*Hn), dim3(32, 8)>>>(x);
    offset_kernel<<<NPIX/8, 256>>>(b_off);
    main_kernel<<<Bn*Hn, 256, SMEM_BYTES>>>(bias, out);
}

// round 7
// speedup vs baseline: 2.2796x; 2.2796x over previous
#include <cuda_runtime.h>
#include <cuda_bf16.h>
#include <cstdint>

#define Bn 8
#define Cn 128
#define Hn 64
#define Wn 64
#define NPIX (Bn*Hn*Wn)          // 32768
#define COUT 128

#define RWB   272                // padded row bytes (128 bf16 = 256B + 16B pad)
#define WHALF (128*RWB)          // 34816: one hi (or lo) weight block per tap
#define WTAP  (2*WHALF)          // 69632: per-tap weight image (hi + lo)

// ---- scratch (allocation-free: __device__ globals) ----
__device__ __align__(16)   float g_xt[NPIX*Cn];        // NHWC copy of x (16 MB)
__device__ __align__(16)   float g_wofft[9*4*Cn];      // w_off transposed: [tap][oc][c]
__device__ __align__(16)   float g_off[NPIX*4];        // per-pixel {off0, off1, s1, s2}
__device__ __align__(1024) unsigned char g_wsplit[9*WTAP];  // per-tap bf16 hi/lo weight images

// ===========================================================================
// PTX helpers — all baseline sm_80/75 features (compile on plain sm_103)
// ===========================================================================
__device__ __forceinline__ uint32_t smem_u32(const void* p) {
    uint32_t a;
    asm("{ .reg .u64 t; cvta.to.shared.u64 t, %1; cvt.u32.u64 %0, t; }" : "=r"(a) : "l"(p));
    return a;
}
__device__ __forceinline__ void cp_async16(uint32_t sdst, const void* gsrc) {
    asm volatile("cp.async.cg.shared.global [%0], [%1], 16;" :: "r"(sdst), "l"(gsrc));
}
#define CP_COMMIT() asm volatile("cp.async.commit_group;")
#define CP_WAIT1()  asm volatile("cp.async.wait_group 1;" ::: "memory")
#define CP_WAIT0()  asm volatile("cp.async.wait_group 0;" ::: "memory")

#define LDSM4(r0,r1,r2,r3,a) \
    asm volatile("ldmatrix.sync.aligned.m8n8.x4.shared.b16 {%0,%1,%2,%3}, [%4];" \
                 : "=r"(r0),"=r"(r1),"=r"(r2),"=r"(r3) : "r"(a))

#define MMA16816(c,a0,a1,a2,a3,b0,b1) \
    asm volatile("mma.sync.aligned.m16n8k16.row.col.f32.bf16.bf16.f32 " \
                 "{%0,%1,%2,%3}, {%4,%5,%6,%7}, {%8,%9}, {%0,%1,%2,%3};" \
                 : "+f"((c)[0]),"+f"((c)[1]),"+f"((c)[2]),"+f"((c)[3]) \
                 : "r"(a0),"r"(a1),"r"(a2),"r"(a3),"r"(b0),"r"(b1))

// ===========================================================================
// Kernel 1: prep — w -> bf16 hi/lo split in padded [o][c] rows; w_off transpose
// ===========================================================================
__global__ void prep_kernel(const float* __restrict__ w, const float* __restrict__ w_off) {
    int tid = blockIdx.x * 256 + threadIdx.x;
    if (tid < 9*Cn*COUT) {
        int k = tid / (Cn*COUT);
        int r = tid % (Cn*COUT);
        int o = r >> 7;           // B-tile row (n)
        int c = r & 127;          // K
        float v = w[(o*Cn + c)*9 + k];
        __nv_bfloat16 hi = __float2bfloat16(v);
        __nv_bfloat16 lo = __float2bfloat16(v - __bfloat162float(hi));
        unsigned char* base = g_wsplit + k*WTAP;
        *(__nv_bfloat16*)(base + o*RWB + c*2)         = hi;
        *(__nv_bfloat16*)(base + WHALF + o*RWB + c*2) = lo;
    }
    if (tid < 9*4*Cn) {
        int tap = tid / (4*Cn);
        int r   = tid % (4*Cn);
        int oc  = r / Cn;
        int c   = r % Cn;
        g_wofft[tid] = w_off[(oc*Cn + c)*9 + tap];
    }
}

// ===========================================================================
// Kernel 2: NCHW -> NHWC transpose of x
// ===========================================================================
__global__ void transpose_kernel(const float* __restrict__ x) {
    __shared__ float tile[32][33];
    int bh = blockIdx.z;
    int b = bh >> 6, h = bh & 63;
    int c0 = blockIdx.y * 32;
    int w0 = blockIdx.x * 32;
    int tx = threadIdx.x, ty = threadIdx.y;
    #pragma unroll
    for (int i = 0; i < 32; i += 8)
        tile[ty + i][tx] = x[((b*Cn + c0 + ty + i)*Hn + h)*Wn + w0 + tx];
    __syncthreads();
    #pragma unroll
    for (int i = 0; i < 32; i += 8)
        g_xt[((bh*Wn) + w0 + ty + i)*Cn + c0 + tx] = tile[tx][ty + i];
}

// ===========================================================================
// Kernel 3: offset conv -> per-pixel params {off0, off1, s1, s2}
// ===========================================================================
__global__ __launch_bounds__(256) void offset_kernel(const float* __restrict__ b_off) {
    __shared__ float sw[9*4*Cn];
    int tid = threadIdx.x;
    for (int i = tid; i < 9*4*Cn; i += 256) sw[i] = g_wofft[i];
    __syncthreads();

    int warp = tid >> 5, lane = tid & 31;
    int pix = blockIdx.x * 8 + warp;
    int b   = pix >> 12;
    int rem = pix & 4095;
    int h   = rem >> 6, w = rem & 63;

    float a0 = 0.f, a1 = 0.f, a2 = 0.f, a3 = 0.f;
    const float4* xt4 = (const float4*)g_xt;

    #pragma unroll
    for (int tap = 0; tap < 9; tap++) {
        int dy = tap/3 - 1, dx = tap%3 - 1;
        int yy = h + dy, xx = w + dx;
        if (yy < 0 || yy >= Hn || xx < 0 || xx >= Wn) continue;
        float4 v = xt4[((b*Hn + yy)*Wn + xx)*(Cn/4) + lane];
        const float4* wv = (const float4*)&sw[tap*4*Cn];
        float4 w0v = wv[0*32 + lane];
        float4 w1v = wv[1*32 + lane];
        float4 w2v = wv[2*32 + lane];
        float4 w3v = wv[3*32 + lane];
        a0 += v.x*w0v.x + v.y*w0v.y + v.z*w0v.z + v.w*w0v.w;
        a1 += v.x*w1v.x + v.y*w1v.y + v.z*w1v.z + v.w*w1v.w;
        a2 += v.x*w2v.x + v.y*w2v.y + v.z*w2v.z + v.w*w2v.w;
        a3 += v.x*w3v.x + v.y*w3v.y + v.z*w3v.z + v.w*w3v.w;
    }
    #pragma unroll
    for (int s = 16; s; s >>= 1) {
        a0 += __shfl_xor_sync(0xffffffffu, a0, s);
        a1 += __shfl_xor_sync(0xffffffffu, a1, s);
        a2 += __shfl_xor_sync(0xffffffffu, a2, s);
        a3 += __shfl_xor_sync(0xffffffffu, a3, s);
    }
    if (lane == 0) {
        float4 r;
        r.x = a0 + b_off[0];
        r.y = a1 + b_off[1];
        r.z = fmaxf(a2 + b_off[2], 0.f) + 1.f;
        r.w = fmaxf(a3 + b_off[3], 0.f) + 1.f;
        ((float4*)g_off)[pix] = r;
    }
}

// ===========================================================================
// Kernel 4: HMMA main. Block = 2 image rows (M=128 px) x 128 out; 8 warps,
// warp tile M32 x N64. Per tap: cp.async w(k+1), sample A (bf16 hi/lo,
// 272B-padded rows), then m16n8k16 bf16 mma, 3 split products, f32 acc in regs.
// smem: s_off 2048 | W 2x69632 | A 69632  = 210,944 B
// ===========================================================================
#define SMEM_W 2048
#define SMEM_A (2048 + 2*WTAP)       // 141312
#define SMEM_BYTES (SMEM_A + WTAP)   // 210944

__global__ __launch_bounds__(256, 1) void main_mma_kernel(const float* __restrict__ bias,
                                                          float* __restrict__ out) {
    extern __shared__ char smem[];
    uint32_t sb = smem_u32(smem);
    int tid  = threadIdx.x;
    int wid  = tid >> 5;
    int lane = tid & 31;
    int blk  = blockIdx.x;              // 256 blocks: (b, row-pair)
    int b    = blk >> 5;
    int h0   = (blk & 31) << 1;

    float4* s_off4 = (float4*)smem;
    if (tid < 128)
        s_off4[tid] = ((const float4*)g_off)[(blk << 7) + tid];

    // preload W tap 0 into buffer 0
    {
        const unsigned char* src = g_wsplit;
        #pragma unroll
        for (int i = 0; i < 17; i++)
            cp_async16(sb + SMEM_W + (tid + i*256)*16, src + (tid + i*256)*16);
        CP_COMMIT();
    }

    // sampling mapping: p = pixel 0..127, half = 64-channel half
    int p    = tid >> 1;
    int half = tid & 1;
    int hh   = h0 + (p >> 6);
    int wc   = p & 63;
    const float4* xt4 = (const float4*)g_xt;

    // mma mapping: 8 warps = 4 M-groups x 2 N-groups
    int mg = wid & 3;        // M: mg*32
    int ng = wid >> 2;       // N: ng*64
    float acc[2][8][4];
    #pragma unroll
    for (int mi = 0; mi < 2; mi++)
        #pragma unroll
        for (int ni = 0; ni < 8; ni++)
            #pragma unroll
            for (int r = 0; r < 4; r++) acc[mi][ni][r] = 0.f;

    // per-lane ldmatrix address components
    uint32_t a_off0 = (uint32_t)((mg*32 + (lane & 15))*RWB + (lane >> 4)*16);
    uint32_t a_off1 = a_off0 + 16*RWB;
    uint32_t b_off[4];
    #pragma unroll
    for (int q = 0; q < 4; q++)
        b_off[q] = (uint32_t)((ng*64 + q*16 + (lane >> 4)*8 + (lane & 7))*RWB
                              + ((lane >> 3) & 1)*16);

    #pragma unroll 1
    for (int k = 0; k < 9; k++) {
        __syncthreads();   // mma(k-1) done reading smem; s_off ready at k=0

        // ---- kick cp.async for w(k+1) into the alternate buffer ----
        if (k < 8) {
            const unsigned char* src = g_wsplit + (k+1)*WTAP;
            uint32_t dst = sb + SMEM_W + (uint32_t)(((k+1)&1))*WTAP;
            #pragma unroll
            for (int i = 0; i < 17; i++)
                cp_async16(dst + (tid + i*256)*16, src + (tid + i*256)*16);
            CP_COMMIT();
        }

        // ---- sample 64 channels of pixel p, split bf16 hi/lo, store padded rows ----
        {
            float4 prm = s_off4[p];
            int by = k/3 - 1, bx = k - (k/3)*3 - 1;
            float sk = (by != 0 && bx != 0) ? prm.z : ((by == 0 && bx == 0) ? 0.f : prm.w);
            float py = (float)hh + (float)by * sk + prm.x;
            float px = (float)wc + (float)bx * sk + prm.y;
            float fy = floorf(py), fx = floorf(px);
            float wy = py - fy,    wx = px - fx;
            int y0 = (int)fy, x0 = (int)fx;
            float cw[4] = {(1.f-wy)*(1.f-wx), (1.f-wy)*wx, wy*(1.f-wx), wy*wx};

            float4 samp[16];
            #pragma unroll
            for (int i = 0; i < 16; i++) samp[i] = make_float4(0.f, 0.f, 0.f, 0.f);

            #pragma unroll
            for (int j = 0; j < 4; j++) {
                int yc = y0 + (j >> 1);
                int xc = x0 + (j & 1);
                if (yc < 0 || yc >= Hn || xc < 0 || xc >= Wn) continue;
                const float4* src = xt4 + ((b*Hn + yc)*Wn + xc)*(Cn/4) + half*16;
                float wj = cw[j];
                #pragma unroll
                for (int i = 0; i < 16; i++) {
                    float4 v = src[i];
                    samp[i].x += wj*v.x; samp[i].y += wj*v.y;
                    samp[i].z += wj*v.z; samp[i].w += wj*v.w;
                }
            }
            char* abase = smem + SMEM_A + p*RWB + half*128;
            #pragma unroll
            for (int i = 0; i < 16; i++) {
                float4 v = samp[i];
                __nv_bfloat162 h01 = __floats2bfloat162_rn(v.x, v.y);
                __nv_bfloat162 h23 = __floats2bfloat162_rn(v.z, v.w);
                float lx = v.x - __bfloat162float(h01.x);
                float ly = v.y - __bfloat162float(h01.y);
                float lz = v.z - __bfloat162float(h23.x);
                float lw = v.w - __bfloat162float(h23.y);
                __nv_bfloat162 l01 = __floats2bfloat162_rn(lx, ly);
                __nv_bfloat162 l23 = __floats2bfloat162_rn(lz, lw);
                *(uint2*)(abase + i*8)         = make_uint2(*(uint32_t*)&h01, *(uint32_t*)&h23);
                *(uint2*)(abase + WHALF + i*8) = make_uint2(*(uint32_t*)&l01, *(uint32_t*)&l23);
            }
        }

        if (k < 8) CP_WAIT1(); else CP_WAIT0();
        __syncthreads();

        // ---- HMMA: 3 split products x 8 K-steps ----
        uint32_t wb = sb + SMEM_W + (uint32_t)(k & 1)*WTAP;
        uint32_t ab = sb + SMEM_A;
        #pragma unroll 1
        for (int kk = 0; kk < 8; kk++) {
            uint32_t ka = (uint32_t)(kk*32);
            uint32_t ah0[4], ah1[4], al0[4], al1[4];
            LDSM4(ah0[0],ah0[1],ah0[2],ah0[3], ab + a_off0 + ka);
            LDSM4(ah1[0],ah1[1],ah1[2],ah1[3], ab + a_off1 + ka);
            LDSM4(al0[0],al0[1],al0[2],al0[3], ab + WHALF + a_off0 + ka);
            LDSM4(al1[0],al1[1],al1[2],al1[3], ab + WHALF + a_off1 + ka);
            #pragma unroll
            for (int q = 0; q < 4; q++) {
                uint32_t bh[4], bl[4];
                LDSM4(bh[0],bh[1],bh[2],bh[3], wb + b_off[q] + ka);
                LDSM4(bl[0],bl[1],bl[2],bl[3], wb + WHALF + b_off[q] + ka);
                #pragma unroll
                for (int s = 0; s < 2; s++) {
                    int ni = q*2 + s;
                    uint32_t bh0 = bh[s*2], bh1 = bh[s*2+1];
                    uint32_t bl0 = bl[s*2], bl1 = bl[s*2+1];
                    MMA16816(acc[0][ni], ah0[0],ah0[1],ah0[2],ah0[3], bh0, bh1);
                    MMA16816(acc[1][ni], ah1[0],ah1[1],ah1[2],ah1[3], bh0, bh1);
                    MMA16816(acc[0][ni], ah0[0],ah0[1],ah0[2],ah0[3], bl0, bl1);
                    MMA16816(acc[1][ni], ah1[0],ah1[1],ah1[2],ah1[3], bl0, bl1);
                    MMA16816(acc[0][ni], al0[0],al0[1],al0[2],al0[3], bh0, bh1);
                    MMA16816(acc[1][ni], al1[0],al1[1],al1[2],al1[3], bh0, bh1);
                }
            }
        }
    }

    // ---- epilogue: C frag (m16n8): c0,c1 row g cols tg*2,+1; c2,c3 row g+8 ----
    {
        int g  = lane >> 2;
        int tg = lane & 3;
        #pragma unroll
        for (int mi = 0; mi < 2; mi++) {
            int m0 = mg*32 + mi*16 + g;
            int m1 = m0 + 8;
            int ha = h0 + (m0 >> 6), wa = m0 & 63;
            int hb = h0 + (m1 >> 6), wb2 = m1 & 63;
            #pragma unroll
            for (int ni = 0; ni < 8; ni++) {
                int o0 = ng*64 + ni*8 + tg*2;
                int o1 = o0 + 1;
                float b0v = __ldg(&bias[o0]);
                float b1v = __ldg(&bias[o1]);
                out[((b*COUT + o0)*Hn + ha)*Wn + wa]  = acc[mi][ni][0] + b0v;
                out[((b*COUT + o1)*Hn + ha)*Wn + wa]  = acc[mi][ni][1] + b1v;
                out[((b*COUT + o0)*Hn + hb)*Wn + wb2] = acc[mi][ni][2] + b0v;
                out[((b*COUT + o1)*Hn + hb)*Wn + wb2] = acc[mi][ni][3] + b1v;
            }
        }
    }
}

// ===========================================================================
extern "C" void kernel_launch(void* const* d_in, const int* in_sizes, int n_in,
                              void* d_out, int out_size) {
    const float* x     = (const float*)d_in[0];
    const float* w_off = (const float*)d_in[1];
    const float* b_off = (const float*)d_in[2];
    const float* w     = (const float*)d_in[3];
    const float* bias  = (const float*)d_in[4];
    float* out = (float*)d_out;

    cudaFuncSetAttribute(main_mma_kernel, cudaFuncAttributeMaxDynamicSharedMemorySize, SMEM_BYTES);

    prep_kernel<<<(9*Cn*COUT + 255)/256, 256>>>(w, w_off);
    transpose_kernel<<<dim3(2, 4, Bn*Hn), dim3(32, 8)>>>(x);
    offset_kernel<<<NPIX/8, 256>>>(b_off);
    main_mma_kernel<<<Bn*Hn/2, 256, SMEM_BYTES>>>(bias, out);
}

// round 8
// speedup vs baseline: 2.7020x; 1.1853x over previous
#include <cuda_runtime.h>
#include <cuda_bf16.h>
#include <cstdint>

#define Bn 8
#define Cn 128
#define Hn 64
#define Wn 64
#define NPIX (Bn*Hn*Wn)          // 32768
#define COUT 128

#define RWB   272                // padded row bytes (128 bf16 = 256B + 16B pad)
#define WHALF (128*RWB)          // 34816: one hi (or lo) block
#define WTAP  (2*WHALF)          // 69632: per-tap image (hi + lo)

// ---- scratch (allocation-free: __device__ globals) ----
__device__ __align__(16)   float g_xt[NPIX*Cn];        // NHWC copy of x (16 MB)
__device__ __align__(16)   float g_wofft[9*4*Cn];      // w_off transposed: [tap][oc][c]
__device__ __align__(16)   float g_off[NPIX*4];        // per-pixel {off0, off1, s1, s2}
__device__ __align__(1024) unsigned char g_wsplit[9*WTAP];  // per-tap bf16 hi/lo weight images

// ===========================================================================
// PTX helpers — baseline sm_80 features only (compile on plain sm_103)
// ===========================================================================
__device__ __forceinline__ uint32_t smem_u32(const void* p) {
    uint32_t a;
    asm("{ .reg .u64 t; cvta.to.shared.u64 t, %1; cvt.u32.u64 %0, t; }" : "=r"(a) : "l"(p));
    return a;
}
__device__ __forceinline__ void cp_async16(uint32_t sdst, const void* gsrc) {
    asm volatile("cp.async.cg.shared.global [%0], [%1], 16;" :: "r"(sdst), "l"(gsrc));
}
#define CP_COMMIT() asm volatile("cp.async.commit_group;")
#define CP_WAIT0()  asm volatile("cp.async.wait_group 0;" ::: "memory")

#define BAR_SYNC(id,cnt)   asm volatile("bar.sync %0, %1;"   :: "r"(id), "r"(cnt) : "memory")
#define BAR_ARRIVE(id,cnt) asm volatile("bar.arrive %0, %1;" :: "r"(id), "r"(cnt) : "memory")

#define LDSM4(r0,r1,r2,r3,a) \
    asm volatile("ldmatrix.sync.aligned.m8n8.x4.shared.b16 {%0,%1,%2,%3}, [%4];" \
                 : "=r"(r0),"=r"(r1),"=r"(r2),"=r"(r3) : "r"(a))

#define MMA16816(c,a0,a1,a2,a3,b0,b1) \
    asm volatile("mma.sync.aligned.m16n8k16.row.col.f32.bf16.bf16.f32 " \
                 "{%0,%1,%2,%3}, {%4,%5,%6,%7}, {%8,%9}, {%0,%1,%2,%3};" \
                 : "+f"((c)[0]),"+f"((c)[1]),"+f"((c)[2]),"+f"((c)[3]) \
                 : "r"(a0),"r"(a1),"r"(a2),"r"(a3),"r"(b0),"r"(b1))

// named barrier ids
#define NB_FULL0  1
#define NB_FULL1  2
#define NB_EMPTY0 3
#define NB_EMPTY1 4
#define NB_CONS   5

// ===========================================================================
// Kernel 1: prep — w -> bf16 hi/lo split in padded [o][c] rows; w_off transpose
// ===========================================================================
__global__ void prep_kernel(const float* __restrict__ w, const float* __restrict__ w_off) {
    int tid = blockIdx.x * 256 + threadIdx.x;
    if (tid < 9*Cn*COUT) {
        int k = tid / (Cn*COUT);
        int r = tid % (Cn*COUT);
        int o = r >> 7;
        int c = r & 127;
        float v = w[(o*Cn + c)*9 + k];
        __nv_bfloat16 hi = __float2bfloat16(v);
        __nv_bfloat16 lo = __float2bfloat16(v - __bfloat162float(hi));
        unsigned char* base = g_wsplit + k*WTAP;
        *(__nv_bfloat16*)(base + o*RWB + c*2)         = hi;
        *(__nv_bfloat16*)(base + WHALF + o*RWB + c*2) = lo;
    }
    if (tid < 9*4*Cn) {
        int tap = tid / (4*Cn);
        int r   = tid % (4*Cn);
        int oc  = r / Cn;
        int c   = r % Cn;
        g_wofft[tid] = w_off[(oc*Cn + c)*9 + tap];
    }
}

// ===========================================================================
// Kernel 2: NCHW -> NHWC transpose of x
// ===========================================================================
__global__ void transpose_kernel(const float* __restrict__ x) {
    __shared__ float tile[32][33];
    int bh = blockIdx.z;
    int b = bh >> 6, h = bh & 63;
    int c0 = blockIdx.y * 32;
    int w0 = blockIdx.x * 32;
    int tx = threadIdx.x, ty = threadIdx.y;
    #pragma unroll
    for (int i = 0; i < 32; i += 8)
        tile[ty + i][tx] = x[((b*Cn + c0 + ty + i)*Hn + h)*Wn + w0 + tx];
    __syncthreads();
    #pragma unroll
    for (int i = 0; i < 32; i += 8)
        g_xt[((bh*Wn) + w0 + ty + i)*Cn + c0 + tx] = tile[tx][ty + i];
}

// ===========================================================================
// Kernel 3: offset conv -> per-pixel params {off0, off1, s1, s2}
// ===========================================================================
__global__ __launch_bounds__(256) void offset_kernel(const float* __restrict__ b_off) {
    __shared__ float sw[9*4*Cn];
    int tid = threadIdx.x;
    for (int i = tid; i < 9*4*Cn; i += 256) sw[i] = g_wofft[i];
    __syncthreads();

    int warp = tid >> 5, lane = tid & 31;
    int pix = blockIdx.x * 8 + warp;
    int b   = pix >> 12;
    int rem = pix & 4095;
    int h   = rem >> 6, w = rem & 63;

    float a0 = 0.f, a1 = 0.f, a2 = 0.f, a3 = 0.f;
    const float4* xt4 = (const float4*)g_xt;

    #pragma unroll
    for (int tap = 0; tap < 9; tap++) {
        int dy = tap/3 - 1, dx = tap%3 - 1;
        int yy = h + dy, xx = w + dx;
        if (yy < 0 || yy >= Hn || xx < 0 || xx >= Wn) continue;
        float4 v = xt4[((b*Hn + yy)*Wn + xx)*(Cn/4) + lane];
        const float4* wv = (const float4*)&sw[tap*4*Cn];
        float4 w0v = wv[0*32 + lane];
        float4 w1v = wv[1*32 + lane];
        float4 w2v = wv[2*32 + lane];
        float4 w3v = wv[3*32 + lane];
        a0 += v.x*w0v.x + v.y*w0v.y + v.z*w0v.z + v.w*w0v.w;
        a1 += v.x*w1v.x + v.y*w1v.y + v.z*w1v.z + v.w*w1v.w;
        a2 += v.x*w2v.x + v.y*w2v.y + v.z*w2v.z + v.w*w2v.w;
        a3 += v.x*w3v.x + v.y*w3v.y + v.z*w3v.z + v.w*w3v.w;
    }
    #pragma unroll
    for (int s = 16; s; s >>= 1) {
        a0 += __shfl_xor_sync(0xffffffffu, a0, s);
        a1 += __shfl_xor_sync(0xffffffffu, a1, s);
        a2 += __shfl_xor_sync(0xffffffffu, a2, s);
        a3 += __shfl_xor_sync(0xffffffffu, a3, s);
    }
    if (lane == 0) {
        float4 r;
        r.x = a0 + b_off[0];
        r.y = a1 + b_off[1];
        r.z = fmaxf(a2 + b_off[2], 0.f) + 1.f;
        r.w = fmaxf(a3 + b_off[3], 0.f) + 1.f;
        ((float4*)g_off)[pix] = r;
    }
}

// ===========================================================================
// Kernel 4: warp-specialized HMMA. 384 threads: warps 0-7 consumers (MMA),
// warps 8-11 producers (bilinear sampling). A tile double-buffered; W
// single-buffered, restaged by consumers via cp.async each tap.
// smem: W 69632 | A0 69632 | A1 69632 = 208,896 B
// ===========================================================================
#define SMEM_W  0
#define SMEM_A0 69632
#define SMEM_A1 139264
#define SMEM_BYTES 208896

__global__ __launch_bounds__(384, 1) void main_ws_kernel(const float* __restrict__ bias,
                                                         float* __restrict__ out) {
    extern __shared__ char smem[];
    uint32_t sb = smem_u32(smem);
    int tid  = threadIdx.x;
    int wid  = tid >> 5;
    int lane = tid & 31;
    int blk  = blockIdx.x;              // 256 blocks: (b, row-pair)
    int b    = blk >> 5;
    int h0   = (blk & 31) << 1;

    if (wid < 8) {
        // ===================== CONSUMER =====================
        // preload W tap 0
        {
            const unsigned char* src = g_wsplit;
            #pragma unroll
            for (int i = 0; i < 17; i++)
                cp_async16(sb + SMEM_W + (tid + i*256)*16, src + (tid + i*256)*16);
            CP_COMMIT();
        }

        int mg = wid & 3;        // M: mg*32
        int ng = wid >> 2;       // N: ng*64
        float acc[2][8][4];
        #pragma unroll
        for (int mi = 0; mi < 2; mi++)
            #pragma unroll
            for (int ni = 0; ni < 8; ni++)
                #pragma unroll
                for (int r = 0; r < 4; r++) acc[mi][ni][r] = 0.f;

        uint32_t a_off0 = (uint32_t)((mg*32 + (lane & 15))*RWB + (lane >> 4)*16);
        uint32_t a_off1 = a_off0 + 16*RWB;
        uint32_t b_off[4];
        #pragma unroll
        for (int q = 0; q < 4; q++)
            b_off[q] = (uint32_t)((ng*64 + q*16 + (lane >> 4)*8 + (lane & 7))*RWB
                                  + ((lane >> 3) & 1)*16);

        #pragma unroll 1
        for (int k = 0; k < 9; k++) {
            int buf = k & 1;
            BAR_SYNC(NB_FULL0 + buf, 384);      // A[buf] filled by producers
            CP_WAIT0();                          // W tap k landed

            uint32_t wb = sb + SMEM_W;
            uint32_t ab = sb + (buf ? SMEM_A1 : SMEM_A0);
            #pragma unroll 1
            for (int kk = 0; kk < 8; kk++) {
                uint32_t ka = (uint32_t)(kk*32);
                uint32_t ah0[4], ah1[4], al0[4], al1[4];
                LDSM4(ah0[0],ah0[1],ah0[2],ah0[3], ab + a_off0 + ka);
                LDSM4(ah1[0],ah1[1],ah1[2],ah1[3], ab + a_off1 + ka);
                LDSM4(al0[0],al0[1],al0[2],al0[3], ab + WHALF + a_off0 + ka);
                LDSM4(al1[0],al1[1],al1[2],al1[3], ab + WHALF + a_off1 + ka);
                #pragma unroll
                for (int q = 0; q < 4; q++) {
                    uint32_t bh[4], bl[4];
                    LDSM4(bh[0],bh[1],bh[2],bh[3], wb + b_off[q] + ka);
                    LDSM4(bl[0],bl[1],bl[2],bl[3], wb + WHALF + b_off[q] + ka);
                    #pragma unroll
                    for (int s = 0; s < 2; s++) {
                        int ni = q*2 + s;
                        uint32_t bh0 = bh[s*2], bh1 = bh[s*2+1];
                        uint32_t bl0 = bl[s*2], bl1 = bl[s*2+1];
                        MMA16816(acc[0][ni], ah0[0],ah0[1],ah0[2],ah0[3], bh0, bh1);
                        MMA16816(acc[1][ni], ah1[0],ah1[1],ah1[2],ah1[3], bh0, bh1);
                        MMA16816(acc[0][ni], ah0[0],ah0[1],ah0[2],ah0[3], bl0, bl1);
                        MMA16816(acc[1][ni], ah1[0],ah1[1],ah1[2],ah1[3], bl0, bl1);
                        MMA16816(acc[0][ni], al0[0],al0[1],al0[2],al0[3], bh0, bh1);
                        MMA16816(acc[1][ni], al1[0],al1[1],al1[2],al1[3], bh0, bh1);
                    }
                }
            }

            if (k < 7) BAR_ARRIVE(NB_EMPTY0 + buf, 384);   // release A[buf]
            if (k < 8) {
                BAR_SYNC(NB_CONS, 256);                    // all consumers done reading W
                const unsigned char* src = g_wsplit + (k+1)*WTAP;
                #pragma unroll
                for (int i = 0; i < 17; i++)
                    cp_async16(sb + SMEM_W + (tid + i*256)*16, src + (tid + i*256)*16);
                CP_COMMIT();
            }
        }

        // ---- epilogue ----
        int g  = lane >> 2;
        int tg = lane & 3;
        #pragma unroll
        for (int mi = 0; mi < 2; mi++) {
            int m0 = mg*32 + mi*16 + g;
            int m1 = m0 + 8;
            int ha = h0 + (m0 >> 6), wa = m0 & 63;
            int hb = h0 + (m1 >> 6), wb2 = m1 & 63;
            #pragma unroll
            for (int ni = 0; ni < 8; ni++) {
                int o0 = ng*64 + ni*8 + tg*2;
                int o1 = o0 + 1;
                float b0v = __ldg(&bias[o0]);
                float b1v = __ldg(&bias[o1]);
                out[((b*COUT + o0)*Hn + ha)*Wn + wa]  = acc[mi][ni][0] + b0v;
                out[((b*COUT + o1)*Hn + ha)*Wn + wa]  = acc[mi][ni][1] + b1v;
                out[((b*COUT + o0)*Hn + hb)*Wn + wb2] = acc[mi][ni][2] + b0v;
                out[((b*COUT + o1)*Hn + hb)*Wn + wb2] = acc[mi][ni][3] + b1v;
            }
        }
    } else {
        // ===================== PRODUCER =====================
        int p  = tid - 256;                 // pixel 0..127
        int hh = h0 + (p >> 6);
        int wc = p & 63;
        float4 prm = ((const float4*)g_off)[(blk << 7) + p];
        const float4* xt4 = (const float4*)g_xt;

        #pragma unroll 1
        for (int k = 0; k < 9; k++) {
            int buf = k & 1;
            if (k >= 2) BAR_SYNC(NB_EMPTY0 + buf, 384);   // consumers done with A[buf]

            int by = k/3 - 1, bx = k - (k/3)*3 - 1;
            float sk = (by != 0 && bx != 0) ? prm.z : ((by == 0 && bx == 0) ? 0.f : prm.w);
            float py = (float)hh + (float)by * sk + prm.x;
            float px = (float)wc + (float)bx * sk + prm.y;
            float fy = floorf(py), fx = floorf(px);
            float wy = py - fy,    wx = px - fx;
            int y0 = (int)fy, x0 = (int)fx;
            float cw[4] = {(1.f-wy)*(1.f-wx), (1.f-wy)*wx, wy*(1.f-wx), wy*wx};

            // corner validity + base offsets (shared by both halves)
            const float4* cptr[4];
            float cwv[4];
            #pragma unroll
            for (int j = 0; j < 4; j++) {
                int yc = y0 + (j >> 1);
                int xc = x0 + (j & 1);
                bool v = (yc >= 0 && yc < Hn && xc >= 0 && xc < Wn);
                cptr[j] = v ? (xt4 + ((b*Hn + yc)*Wn + xc)*(Cn/4)) : (const float4*)0;
                cwv[j]  = v ? cw[j] : 0.f;
            }

            char* abase = smem + (buf ? SMEM_A1 : SMEM_A0) + p*RWB;
            #pragma unroll 1
            for (int half = 0; half < 2; half++) {
                float4 samp[16];
                #pragma unroll
                for (int i = 0; i < 16; i++) samp[i] = make_float4(0.f, 0.f, 0.f, 0.f);
                #pragma unroll
                for (int j = 0; j < 4; j++) {
                    if (!cptr[j]) continue;
                    const float4* src = cptr[j] + half*16;
                    float wj = cwv[j];
                    #pragma unroll
                    for (int i = 0; i < 16; i++) {
                        float4 v = src[i];
                        samp[i].x += wj*v.x; samp[i].y += wj*v.y;
                        samp[i].z += wj*v.z; samp[i].w += wj*v.w;
                    }
                }
                char* ab = abase + half*128;
                #pragma unroll
                for (int i = 0; i < 16; i++) {
                    float4 v = samp[i];
                    __nv_bfloat162 h01 = __floats2bfloat162_rn(v.x, v.y);
                    __nv_bfloat162 h23 = __floats2bfloat162_rn(v.z, v.w);
                    float lx = v.x - __bfloat162float(h01.x);
                    float ly = v.y - __bfloat162float(h01.y);
                    float lz = v.z - __bfloat162float(h23.x);
                    float lw = v.w - __bfloat162float(h23.y);
                    __nv_bfloat162 l01 = __floats2bfloat162_rn(lx, ly);
                    __nv_bfloat162 l23 = __floats2bfloat162_rn(lz, lw);
                    *(uint2*)(ab + i*8)         = make_uint2(*(uint32_t*)&h01, *(uint32_t*)&h23);
                    *(uint2*)(ab + WHALF + i*8) = make_uint2(*(uint32_t*)&l01, *(uint32_t*)&l23);
                }
            }
            BAR_ARRIVE(NB_FULL0 + buf, 384);   // A[buf] ready
        }
    }
}

// ===========================================================================
extern "C" void kernel_launch(void* const* d_in, const int* in_sizes, int n_in,
                              void* d_out, int out_size) {
    const float* x     = (const float*)d_in[0];
    const float* w_off = (const float*)d_in[1];
    const float* b_off = (const float*)d_in[2];
    const float* w     = (const float*)d_in[3];
    const float* bias  = (const float*)d_in[4];
    float* out = (float*)d_out;

    cudaFuncSetAttribute(main_ws_kernel, cudaFuncAttributeMaxDynamicSharedMemorySize, SMEM_BYTES);

    prep_kernel<<<(9*Cn*COUT + 255)/256, 256>>>(w, w_off);
    transpose_kernel<<<dim3(2, 4, Bn*Hn), dim3(32, 8)>>>(x);
    offset_kernel<<<NPIX/8, 256>>>(b_off);
    main_ws_kernel<<<Bn*Hn/2, 384, SMEM_BYTES>>>(bias, out);
}

// round 9
// speedup vs baseline: 2.7396x; 1.0139x over previous
#include <cuda_runtime.h>
#include <cuda_bf16.h>
#include <cstdint>

#define Bn 8
#define Cn 128
#define Hn 64
#define Wn 64
#define NPIX (Bn*Hn*Wn)          // 32768
#define COUT 128

#define RWB   272                // padded row bytes (128 bf16 = 256B + 16B pad)
#define WHALF (128*RWB)          // 34816: one hi (or lo) block
#define WTAP  (2*WHALF)          // 69632: per-tap image (hi + lo)

// ---- scratch (allocation-free: __device__ globals) ----
__device__ __align__(16)   float g_xt[NPIX*Cn];        // NHWC copy of x (16 MB)
__device__ __align__(16)   float g_wofft[9*4*Cn];      // w_off transposed: [tap][oc][c]
__device__ __align__(16)   float g_off[NPIX*4];        // per-pixel {off0, off1, s1, s2}
__device__ __align__(1024) unsigned char g_wsplit[9*WTAP];  // per-tap bf16 hi/lo weight images

// ===========================================================================
// PTX helpers — baseline sm_80 features only (compile on plain sm_103)
// ===========================================================================
__device__ __forceinline__ uint32_t smem_u32(const void* p) {
    uint32_t a;
    asm("{ .reg .u64 t; cvta.to.shared.u64 t, %1; cvt.u32.u64 %0, t; }" : "=r"(a) : "l"(p));
    return a;
}
__device__ __forceinline__ void cp_async16(uint32_t sdst, const void* gsrc) {
    asm volatile("cp.async.cg.shared.global [%0], [%1], 16;" :: "r"(sdst), "l"(gsrc));
}
#define CP_COMMIT() asm volatile("cp.async.commit_group;")
#define CP_WAIT0()  asm volatile("cp.async.wait_group 0;" ::: "memory")

#define BAR_SYNC(id,cnt)   asm volatile("bar.sync %0, %1;"   :: "r"(id), "r"(cnt) : "memory")
#define BAR_ARRIVE(id,cnt) asm volatile("bar.arrive %0, %1;" :: "r"(id), "r"(cnt) : "memory")

#define LDSM4(r0,r1,r2,r3,a) \
    asm volatile("ldmatrix.sync.aligned.m8n8.x4.shared.b16 {%0,%1,%2,%3}, [%4];" \
                 : "=r"(r0),"=r"(r1),"=r"(r2),"=r"(r3) : "r"(a))

#define MMA16816(c,a0,a1,a2,a3,b0,b1) \
    asm volatile("mma.sync.aligned.m16n8k16.row.col.f32.bf16.bf16.f32 " \
                 "{%0,%1,%2,%3}, {%4,%5,%6,%7}, {%8,%9}, {%0,%1,%2,%3};" \
                 : "+f"((c)[0]),"+f"((c)[1]),"+f"((c)[2]),"+f"((c)[3]) \
                 : "r"(a0),"r"(a1),"r"(a2),"r"(a3),"r"(b0),"r"(b1))

// named barrier ids
#define NB_FULL0  1
#define NB_FULL1  2
#define NB_EMPTY0 3
#define NB_EMPTY1 4
#define NB_CONS   5

// ===========================================================================
// Kernel 1: prep — w -> bf16 hi/lo split in padded [o][c] rows; w_off transpose
// ===========================================================================
__global__ void prep_kernel(const float* __restrict__ w, const float* __restrict__ w_off) {
    int tid = blockIdx.x * 256 + threadIdx.x;
    if (tid < 9*Cn*COUT) {
        int k = tid / (Cn*COUT);
        int r = tid % (Cn*COUT);
        int o = r >> 7;
        int c = r & 127;
        float v = w[(o*Cn + c)*9 + k];
        __nv_bfloat16 hi = __float2bfloat16(v);
        __nv_bfloat16 lo = __float2bfloat16(v - __bfloat162float(hi));
        unsigned char* base = g_wsplit + k*WTAP;
        *(__nv_bfloat16*)(base + o*RWB + c*2)         = hi;
        *(__nv_bfloat16*)(base + WHALF + o*RWB + c*2) = lo;
    }
    if (tid < 9*4*Cn) {
        int tap = tid / (4*Cn);
        int r   = tid % (4*Cn);
        int oc  = r / Cn;
        int c   = r % Cn;
        g_wofft[tid] = w_off[(oc*Cn + c)*9 + tap];
    }
}

// ===========================================================================
// Kernel 2: NCHW -> NHWC transpose of x
// ===========================================================================
__global__ void transpose_kernel(const float* __restrict__ x) {
    __shared__ float tile[32][33];
    int bh = blockIdx.z;
    int b = bh >> 6, h = bh & 63;
    int c0 = blockIdx.y * 32;
    int w0 = blockIdx.x * 32;
    int tx = threadIdx.x, ty = threadIdx.y;
    #pragma unroll
    for (int i = 0; i < 32; i += 8)
        tile[ty + i][tx] = x[((b*Cn + c0 + ty + i)*Hn + h)*Wn + w0 + tx];
    __syncthreads();
    #pragma unroll
    for (int i = 0; i < 32; i += 8)
        g_xt[((bh*Wn) + w0 + ty + i)*Cn + c0 + tx] = tile[tx][ty + i];
}

// ===========================================================================
// Kernel 3: offset conv -> per-pixel params {off0, off1, s1, s2}
// ===========================================================================
__global__ __launch_bounds__(256) void offset_kernel(const float* __restrict__ b_off) {
    __shared__ float sw[9*4*Cn];
    int tid = threadIdx.x;
    for (int i = tid; i < 9*4*Cn; i += 256) sw[i] = g_wofft[i];
    __syncthreads();

    int warp = tid >> 5, lane = tid & 31;
    int pix = blockIdx.x * 8 + warp;
    int b   = pix >> 12;
    int rem = pix & 4095;
    int h   = rem >> 6, w = rem & 63;

    float a0 = 0.f, a1 = 0.f, a2 = 0.f, a3 = 0.f;
    const float4* xt4 = (const float4*)g_xt;

    #pragma unroll
    for (int tap = 0; tap < 9; tap++) {
        int dy = tap/3 - 1, dx = tap%3 - 1;
        int yy = h + dy, xx = w + dx;
        if (yy < 0 || yy >= Hn || xx < 0 || xx >= Wn) continue;
        float4 v = xt4[((b*Hn + yy)*Wn + xx)*(Cn/4) + lane];
        const float4* wv = (const float4*)&sw[tap*4*Cn];
        float4 w0v = wv[0*32 + lane];
        float4 w1v = wv[1*32 + lane];
        float4 w2v = wv[2*32 + lane];
        float4 w3v = wv[3*32 + lane];
        a0 += v.x*w0v.x + v.y*w0v.y + v.z*w0v.z + v.w*w0v.w;
        a1 += v.x*w1v.x + v.y*w1v.y + v.z*w1v.z + v.w*w1v.w;
        a2 += v.x*w2v.x + v.y*w2v.y + v.z*w2v.z + v.w*w2v.w;
        a3 += v.x*w3v.x + v.y*w3v.y + v.z*w3v.z + v.w*w3v.w;
    }
    #pragma unroll
    for (int s = 16; s; s >>= 1) {
        a0 += __shfl_xor_sync(0xffffffffu, a0, s);
        a1 += __shfl_xor_sync(0xffffffffu, a1, s);
        a2 += __shfl_xor_sync(0xffffffffu, a2, s);
        a3 += __shfl_xor_sync(0xffffffffu, a3, s);
    }
    if (lane == 0) {
        float4 r;
        r.x = a0 + b_off[0];
        r.y = a1 + b_off[1];
        r.z = fmaxf(a2 + b_off[2], 0.f) + 1.f;
        r.w = fmaxf(a3 + b_off[3], 0.f) + 1.f;
        ((float4*)g_off)[pix] = r;
    }
}

// ===========================================================================
// Kernel 4: warp-specialized HMMA. 384 threads: warps 0-7 consumers (MMA),
// warps 8-11 producers (bilinear sampling, COALESCED: 8 lanes per pixel).
// A tile double-buffered; W single-buffered, restaged by consumers.
// smem: W 69632 | A0 69632 | A1 69632 = 208,896 B
// ===========================================================================
#define SMEM_W  0
#define SMEM_A0 69632
#define SMEM_A1 139264
#define SMEM_BYTES 208896

__global__ __launch_bounds__(384, 1) void main_ws_kernel(const float* __restrict__ bias,
                                                         float* __restrict__ out) {
    extern __shared__ char smem[];
    uint32_t sb = smem_u32(smem);
    int tid  = threadIdx.x;
    int wid  = tid >> 5;
    int lane = tid & 31;
    int blk  = blockIdx.x;              // 256 blocks: (b, row-pair)
    int b    = blk >> 5;
    int h0   = (blk & 31) << 1;

    if (wid < 8) {
        // ===================== CONSUMER =====================
        // preload W tap 0
        {
            const unsigned char* src = g_wsplit;
            #pragma unroll
            for (int i = 0; i < 17; i++)
                cp_async16(sb + SMEM_W + (tid + i*256)*16, src + (tid + i*256)*16);
            CP_COMMIT();
        }

        int mg = wid & 3;        // M: mg*32
        int ng = wid >> 2;       // N: ng*64
        float acc[2][8][4];
        #pragma unroll
        for (int mi = 0; mi < 2; mi++)
            #pragma unroll
            for (int ni = 0; ni < 8; ni++)
                #pragma unroll
                for (int r = 0; r < 4; r++) acc[mi][ni][r] = 0.f;

        uint32_t a_off0 = (uint32_t)((mg*32 + (lane & 15))*RWB + (lane >> 4)*16);
        uint32_t a_off1 = a_off0 + 16*RWB;
        uint32_t b_off[4];
        #pragma unroll
        for (int q = 0; q < 4; q++)
            b_off[q] = (uint32_t)((ng*64 + q*16 + (lane >> 4)*8 + (lane & 7))*RWB
                                  + ((lane >> 3) & 1)*16);

        #pragma unroll 1
        for (int k = 0; k < 9; k++) {
            int buf = k & 1;
            BAR_SYNC(NB_FULL0 + buf, 384);      // A[buf] filled by producers
            CP_WAIT0();                          // W tap k landed

            uint32_t wb = sb + SMEM_W;
            uint32_t ab = sb + (buf ? SMEM_A1 : SMEM_A0);
            #pragma unroll 1
            for (int kk = 0; kk < 8; kk++) {
                uint32_t ka = (uint32_t)(kk*32);
                uint32_t ah0[4], ah1[4], al0[4], al1[4];
                LDSM4(ah0[0],ah0[1],ah0[2],ah0[3], ab + a_off0 + ka);
                LDSM4(ah1[0],ah1[1],ah1[2],ah1[3], ab + a_off1 + ka);
                LDSM4(al0[0],al0[1],al0[2],al0[3], ab + WHALF + a_off0 + ka);
                LDSM4(al1[0],al1[1],al1[2],al1[3], ab + WHALF + a_off1 + ka);
                #pragma unroll
                for (int q = 0; q < 4; q++) {
                    uint32_t bh[4], bl[4];
                    LDSM4(bh[0],bh[1],bh[2],bh[3], wb + b_off[q] + ka);
                    LDSM4(bl[0],bl[1],bl[2],bl[3], wb + WHALF + b_off[q] + ka);
                    #pragma unroll
                    for (int s = 0; s < 2; s++) {
                        int ni = q*2 + s;
                        uint32_t bh0 = bh[s*2], bh1 = bh[s*2+1];
                        uint32_t bl0 = bl[s*2], bl1 = bl[s*2+1];
                        MMA16816(acc[0][ni], ah0[0],ah0[1],ah0[2],ah0[3], bh0, bh1);
                        MMA16816(acc[1][ni], ah1[0],ah1[1],ah1[2],ah1[3], bh0, bh1);
                        MMA16816(acc[0][ni], ah0[0],ah0[1],ah0[2],ah0[3], bl0, bl1);
                        MMA16816(acc[1][ni], ah1[0],ah1[1],ah1[2],ah1[3], bl0, bl1);
                        MMA16816(acc[0][ni], al0[0],al0[1],al0[2],al0[3], bh0, bh1);
                        MMA16816(acc[1][ni], al1[0],al1[1],al1[2],al1[3], bh0, bh1);
                    }
                }
            }

            if (k < 7) BAR_ARRIVE(NB_EMPTY0 + buf, 384);   // release A[buf]
            if (k < 8) {
                BAR_SYNC(NB_CONS, 256);                    // all consumers done reading W
                const unsigned char* src = g_wsplit + (k+1)*WTAP;
                #pragma unroll
                for (int i = 0; i < 17; i++)
                    cp_async16(sb + SMEM_W + (tid + i*256)*16, src + (tid + i*256)*16);
                CP_COMMIT();
            }
        }

        // ---- epilogue ----
        int g  = lane >> 2;
        int tg = lane & 3;
        #pragma unroll
        for (int mi = 0; mi < 2; mi++) {
            int m0 = mg*32 + mi*16 + g;
            int m1 = m0 + 8;
            int ha = h0 + (m0 >> 6), wa = m0 & 63;
            int hb = h0 + (m1 >> 6), wb2 = m1 & 63;
            #pragma unroll
            for (int ni = 0; ni < 8; ni++) {
                int o0 = ng*64 + ni*8 + tg*2;
                int o1 = o0 + 1;
                float b0v = __ldg(&bias[o0]);
                float b1v = __ldg(&bias[o1]);
                out[((b*COUT + o0)*Hn + ha)*Wn + wa]  = acc[mi][ni][0] + b0v;
                out[((b*COUT + o1)*Hn + ha)*Wn + wa]  = acc[mi][ni][1] + b1v;
                out[((b*COUT + o0)*Hn + hb)*Wn + wb2] = acc[mi][ni][2] + b0v;
                out[((b*COUT + o1)*Hn + hb)*Wn + wb2] = acc[mi][ni][3] + b1v;
            }
        }
    } else {
        // ===================== PRODUCER (coalesced) =====================
        // thread t: channel-group g = t&7 (float4 idx {g, g+8, g+16, g+24}),
        // pixel-group pg = t>>3 -> pixels pg*8 .. pg*8+7.
        // For fixed (s, i), the 8 lanes of a group read one contiguous 128B line.
        int t  = tid - 256;                 // 0..127
        int g  = t & 7;
        int pg = t >> 3;

        float4 prms[8];
        #pragma unroll
        for (int s = 0; s < 8; s++)
            prms[s] = ((const float4*)g_off)[(blk << 7) + pg*8 + s];

        const float4* xt4 = (const float4*)g_xt;

        #pragma unroll 1
        for (int k = 0; k < 9; k++) {
            int buf = k & 1;
            if (k >= 2) BAR_SYNC(NB_EMPTY0 + buf, 384);   // consumers done with A[buf]

            int by = k/3 - 1, bx = k - (k/3)*3 - 1;
            char* abuf = smem + (buf ? SMEM_A1 : SMEM_A0);

            #pragma unroll 1
            for (int s = 0; s < 8; s++) {
                int p  = pg*8 + s;
                int hh = h0 + (p >> 6);
                int wc = p & 63;
                float4 prm = prms[s];
                float sk = (by != 0 && bx != 0) ? prm.z : ((by == 0 && bx == 0) ? 0.f : prm.w);
                float py = (float)hh + (float)by * sk + prm.x;
                float px = (float)wc + (float)bx * sk + prm.y;
                float fy = floorf(py), fx = floorf(px);
                float wy = py - fy,    wx = px - fx;
                int y0 = (int)fy, x0 = (int)fx;
                float cw[4] = {(1.f-wy)*(1.f-wx), (1.f-wy)*wx, wy*(1.f-wx), wy*wx};

                float4 samp[4];
                #pragma unroll
                for (int i = 0; i < 4; i++) samp[i] = make_float4(0.f, 0.f, 0.f, 0.f);

                #pragma unroll
                for (int j = 0; j < 4; j++) {
                    int yc = y0 + (j >> 1);
                    int xc = x0 + (j & 1);
                    if (yc < 0 || yc >= Hn || xc < 0 || xc >= Wn) continue;
                    const float4* src = xt4 + ((b*Hn + yc)*Wn + xc)*(Cn/4);
                    float wj = cw[j];
                    #pragma unroll
                    for (int i = 0; i < 4; i++) {
                        float4 v = src[g + i*8];
                        samp[i].x += wj*v.x; samp[i].y += wj*v.y;
                        samp[i].z += wj*v.z; samp[i].w += wj*v.w;
                    }
                }
                char* ab = abuf + p*RWB;
                #pragma unroll
                for (int i = 0; i < 4; i++) {
                    float4 v = samp[i];
                    __nv_bfloat162 h01 = __floats2bfloat162_rn(v.x, v.y);
                    __nv_bfloat162 h23 = __floats2bfloat162_rn(v.z, v.w);
                    float lx = v.x - __bfloat162float(h01.x);
                    float ly = v.y - __bfloat162float(h01.y);
                    float lz = v.z - __bfloat162float(h23.x);
                    float lw = v.w - __bfloat162float(h23.y);
                    __nv_bfloat162 l01 = __floats2bfloat162_rn(lx, ly);
                    __nv_bfloat162 l23 = __floats2bfloat162_rn(lz, lw);
                    int boff = (g + i*8) * 8;            // byte offset of channel 4*(g+i*8)
                    *(uint2*)(ab + boff)         = make_uint2(*(uint32_t*)&h01, *(uint32_t*)&h23);
                    *(uint2*)(ab + WHALF + boff) = make_uint2(*(uint32_t*)&l01, *(uint32_t*)&l23);
                }
            }
            BAR_ARRIVE(NB_FULL0 + buf, 384);   // A[buf] ready
        }
    }
}

// ===========================================================================
extern "C" void kernel_launch(void* const* d_in, const int* in_sizes, int n_in,
                              void* d_out, int out_size) {
    const float* x     = (const float*)d_in[0];
    const float* w_off = (const float*)d_in[1];
    const float* b_off = (const float*)d_in[2];
    const float* w     = (const float*)d_in[3];
    const float* bias  = (const float*)d_in[4];
    float* out = (float*)d_out;

    cudaFuncSetAttribute(main_ws_kernel, cudaFuncAttributeMaxDynamicSharedMemorySize, SMEM_BYTES);

    prep_kernel<<<(9*Cn*COUT + 255)/256, 256>>>(w, w_off);
    transpose_kernel<<<dim3(2, 4, Bn*Hn), dim3(32, 8)>>>(x);
    offset_kernel<<<NPIX/8, 256>>>(b_off);
    main_ws_kernel<<<Bn*Hn/2, 384, SMEM_BYTES>>>(bias, out);
}